// round 1
// baseline (speedup 1.0000x reference)
#include <cuda_runtime.h>
#include <cuda_bf16.h>
#include <math.h>

// Problem constants
#define BATCH 2
#define SEQ   2048
#define EMB   2048
#define HEADS 16
#define HDIM  128

// Scratch buffers (allocation-free rule: __device__ globals)
__device__ float g_q[BATCH * SEQ * EMB];
__device__ float g_k[BATCH * SEQ * EMB];
__device__ float g_v[BATCH * SEQ * EMB];
__device__ float g_att[BATCH * SEQ * EMB];

// ---------------------------------------------------------------------------
// SGEMM (NT): C[M,N] = A[M,K] * B[N,K]^T, all row-major, fp32.
// BM=BN=64, BK=16, 256 threads, 4x4 per thread.
// ---------------------------------------------------------------------------
__global__ __launch_bounds__(256)
void sgemm_nt(const float* __restrict__ A, const float* __restrict__ B,
              float* __restrict__ C, int M, int N, int K) {
    __shared__ float As[16][68];
    __shared__ float Bs[16][68];

    const int tid = threadIdx.x;
    const int bm = blockIdx.y * 64;
    const int bn = blockIdx.x * 64;
    const int tx = tid & 15;        // N direction
    const int ty = tid >> 4;        // M direction
    const int lr = tid >> 2;        // loader row 0..63
    const int lk = (tid & 3) << 2;  // loader k offset 0,4,8,12

    float acc[4][4];
#pragma unroll
    for (int i = 0; i < 4; i++)
#pragma unroll
        for (int j = 0; j < 4; j++) acc[i][j] = 0.0f;

    const float* Arow = A + (size_t)(bm + lr) * K + lk;
    const float* Brow = B + (size_t)(bn + lr) * K + lk;

    for (int k0 = 0; k0 < K; k0 += 16) {
        float4 a4 = *(const float4*)(Arow + k0);
        float4 b4 = *(const float4*)(Brow + k0);
        As[lk + 0][lr] = a4.x; As[lk + 1][lr] = a4.y;
        As[lk + 2][lr] = a4.z; As[lk + 3][lr] = a4.w;
        Bs[lk + 0][lr] = b4.x; Bs[lk + 1][lr] = b4.y;
        Bs[lk + 2][lr] = b4.z; Bs[lk + 3][lr] = b4.w;
        __syncthreads();

#pragma unroll
        for (int kk = 0; kk < 16; kk++) {
            float ar[4], br[4];
#pragma unroll
            for (int i = 0; i < 4; i++) ar[i] = As[kk][ty * 4 + i];
#pragma unroll
            for (int j = 0; j < 4; j++) br[j] = Bs[kk][tx * 4 + j];
#pragma unroll
            for (int i = 0; i < 4; i++)
#pragma unroll
                for (int j = 0; j < 4; j++)
                    acc[i][j] = fmaf(ar[i], br[j], acc[i][j]);
        }
        __syncthreads();
    }

#pragma unroll
    for (int i = 0; i < 4; i++) {
        float4 r;
        r.x = acc[i][0]; r.y = acc[i][1]; r.z = acc[i][2]; r.w = acc[i][3];
        *(float4*)(C + (size_t)(bm + ty * 4 + i) * N + bn + tx * 4) = r;
    }
}

// ---------------------------------------------------------------------------
// xpos rotary on q and k (in place). One thread per (b,s,h,pair).
// ---------------------------------------------------------------------------
__global__ __launch_bounds__(256)
void xpos_kernel() {
    int idx = blockIdx.x * 256 + threadIdx.x;   // over BATCH*SEQ*HEADS*64
    int pair = idx & 63;
    int h = (idx >> 6) & (HEADS - 1);
    int bs = idx >> 10;                          // 0 .. BATCH*SEQ-1
    int s = bs & (SEQ - 1);

    float seq = (float)(s - SEQ / 2) * (1.0f / 512.0f);   // SCALE_BASE=512
    float dr = 2.0f * (float)(pair + 1);
    float theta = powf(1.0e-4f, dr * (1.0f / 128.0f));
    float zeta = (dr * (1.0f / 64.0f) + 51.2f) * (1.0f / 52.2f); // alpha=51.2
    float ang = seq * theta;
    float c = cosf(ang);
    float sn = sinf(ang);
    float t = powf(zeta, seq);
    float it = 1.0f / t;

    size_t base = (size_t)bs * EMB + h * HDIM + pair * 2;
    float2 qv = *(float2*)(g_q + base);
    float2 kv = *(float2*)(g_k + base);
    float2 qo, ko;
    // rotate_every_two: out[2i] = -x[2i+1], out[2i+1] = x[2i]
    qo.x = (qv.x * c - qv.y * sn) * t;
    qo.y = (qv.y * c + qv.x * sn) * t;
    ko.x = (kv.x * c - kv.y * sn) * it;
    ko.y = (kv.y * c + kv.x * sn) * it;
    *(float2*)(g_q + base) = qo;
    *(float2*)(g_k + base) = ko;
}

// ---------------------------------------------------------------------------
// Causal flash attention, fp32.
// Block = 512 threads = 128 query rows x 4-thread groups (32 dims each).
// K/V tiles of 64 keys in dynamic smem (64 KB).
// grid = BATCH*HEADS*(SEQ/128) = 512 blocks; long (high-qt) blocks first.
// ---------------------------------------------------------------------------
__global__ __launch_bounds__(512, 1)
void attn_kernel() {
    extern __shared__ float sm[];
    float4* Ks4 = (float4*)sm;                 // [64][32] float4
    float4* Vs4 = (float4*)(sm + 64 * 128);    // [64][32] float4

    const int bid = blockIdx.x;
    const int qt = (SEQ / 128 - 1) - (bid >> 5);   // 15..0, long blocks first
    const int bh = bid & 31;
    const int b = bh >> 4;
    const int h = bh & (HEADS - 1);

    const int tid = threadIdx.x;
    const int rloc = tid >> 2;          // 0..127 query row within tile
    const int g = tid & 3;              // dim group: dims [g*32, g*32+32)
    const int r = qt * 128 + rloc;      // global query position
    const unsigned gmask = 0xFu << ((tid & 31) & ~3);

    // q fragment -> registers
    const float* qbase = g_q + ((size_t)b * SEQ + r) * EMB + h * HDIM + g * 32;
    float4 q4[8];
#pragma unroll
    for (int i = 0; i < 8; i++) q4[i] = ((const float4*)qbase)[i];

    float4 o4[8];
#pragma unroll
    for (int i = 0; i < 8; i++) o4[i] = make_float4(0.f, 0.f, 0.f, 0.f);
    float m = -3.0e38f, l = 0.0f;
    const float scale = 0.08838834764831845f;   // 1/sqrt(128)

    const float* kg = g_k + (size_t)b * SEQ * EMB + h * HDIM;
    const float* vg = g_v + (size_t)b * SEQ * EMB + h * HDIM;

    const int nkt = qt * 2 + 2;   // key tiles of 64 covering [0, qt*128+128)
    for (int kt = 0; kt < nkt; kt++) {
        __syncthreads();
        // cooperative tile load: 64 rows x 32 float4, 512 threads -> 4 each
#pragma unroll
        for (int i = 0; i < 4; i++) {
            int id = tid + i * 512;          // 0..2047
            int row = id >> 5;
            int c4 = id & 31;
            size_t goff = (size_t)(kt * 64 + row) * EMB + c4 * 4;
            Ks4[row * 32 + c4] = *(const float4*)(kg + goff);
            Vs4[row * 32 + c4] = *(const float4*)(vg + goff);
        }
        __syncthreads();

        int jmax = r - kt * 64 + 1;
        if (jmax > 64) jmax = 64;
        for (int j = 0; j < jmax; j++) {
            const float4* krow = Ks4 + j * 32 + g * 8;
            float p0 = 0.f, p1 = 0.f, p2 = 0.f, p3 = 0.f;
#pragma unroll
            for (int i = 0; i < 8; i++) {
                float4 kv = krow[i];
                p0 = fmaf(q4[i].x, kv.x, p0);
                p1 = fmaf(q4[i].y, kv.y, p1);
                p2 = fmaf(q4[i].z, kv.z, p2);
                p3 = fmaf(q4[i].w, kv.w, p3);
            }
            float sdot = (p0 + p1) + (p2 + p3);
            sdot += __shfl_xor_sync(gmask, sdot, 1);
            sdot += __shfl_xor_sync(gmask, sdot, 2);
            float sc = sdot * scale;

            float mn = fmaxf(m, sc);
            float cf = __expf(m - mn);
            float p = __expf(sc - mn);
            l = l * cf + p;
            m = mn;

            const float4* vrow = Vs4 + j * 32 + g * 8;
#pragma unroll
            for (int i = 0; i < 8; i++) {
                float4 vv = vrow[i];
                o4[i].x = fmaf(p, vv.x, o4[i].x * cf);
                o4[i].y = fmaf(p, vv.y, o4[i].y * cf);
                o4[i].z = fmaf(p, vv.z, o4[i].z * cf);
                o4[i].w = fmaf(p, vv.w, o4[i].w * cf);
            }
        }
    }

    float inv = 1.0f / l;
    float* ob = g_att + ((size_t)b * SEQ + r) * EMB + h * HDIM + g * 32;
#pragma unroll
    for (int i = 0; i < 8; i++) {
        float4 w;
        w.x = o4[i].x * inv; w.y = o4[i].y * inv;
        w.z = o4[i].z * inv; w.w = o4[i].w * inv;
        ((float4*)ob)[i] = w;
    }
}

// ---------------------------------------------------------------------------
// Launch
// ---------------------------------------------------------------------------
extern "C" void kernel_launch(void* const* d_in, const int* in_sizes, int n_in,
                              void* d_out, int out_size) {
    const float* act = (const float*)d_in[0];
    const float* Wq  = (const float*)d_in[1];
    const float* Wk  = (const float*)d_in[2];
    const float* Wv  = (const float*)d_in[3];
    const float* Wo  = (const float*)d_in[4];
    float* out = (float*)d_out;

    float *qp, *kp, *vp, *ap;
    cudaGetSymbolAddress((void**)&qp, g_q);
    cudaGetSymbolAddress((void**)&kp, g_k);
    cudaGetSymbolAddress((void**)&vp, g_v);
    cudaGetSymbolAddress((void**)&ap, g_att);

    const int M = BATCH * SEQ;   // 4096
    const int N = EMB;           // 2048
    const int K = EMB;           // 2048
    dim3 ggrid(N / 64, M / 64);

    sgemm_nt<<<ggrid, 256>>>(act, Wq, qp, M, N, K);
    sgemm_nt<<<ggrid, 256>>>(act, Wk, kp, M, N, K);
    sgemm_nt<<<ggrid, 256>>>(act, Wv, vp, M, N, K);

    int nrot = BATCH * SEQ * HEADS * 64;  // pairs
    xpos_kernel<<<nrot / 256, 256>>>();

    static int smem_set = 0;
    cudaFuncSetAttribute(attn_kernel, cudaFuncAttributeMaxDynamicSharedMemorySize,
                         64 * 128 * 4 * 2);
    (void)smem_set;
    attn_kernel<<<BATCH * HEADS * (SEQ / 128), 512, 64 * 128 * 4 * 2>>>();

    sgemm_nt<<<ggrid, 256>>>(ap, Wo, out, M, N, K);
}

// round 3
// speedup vs baseline: 1.3223x; 1.3223x over previous
#include <cuda_runtime.h>
#include <cuda_bf16.h>
#include <math.h>
#include <stdint.h>

// Problem constants
#define BATCH 2
#define SEQ   2048
#define EMB   2048
#define HEADS 16
#define HDIM  128

// Scratch buffers (allocation-free rule: __device__ globals)
__device__ float g_q[BATCH * SEQ * EMB];
__device__ float g_k[BATCH * SEQ * EMB];
__device__ float g_v[BATCH * SEQ * EMB];
__device__ float g_att[BATCH * SEQ * EMB];   // attention out (tf32-rounded)
__device__ float g_actr[BATCH * SEQ * EMB];  // tf32-rounded activations
__device__ float g_w[EMB * EMB];             // tf32-rounded weight (reused 4x)

// ---------------------------------------------------------------------------
// helpers
// ---------------------------------------------------------------------------
__device__ __forceinline__ uint32_t smem_u32(const void* p) {
    uint32_t a;
    asm("{ .reg .u64 t; cvta.to.shared.u64 t, %1; cvt.u32.u64 %0, t; }"
        : "=r"(a) : "l"(p));
    return a;
}

__device__ __forceinline__ float rna_tf32(float x) {
    float r;
    asm("cvt.rna.tf32.f32 %0, %1;" : "=f"(r) : "f"(x));
    return r;
}

#define CP_ASYNC16(saddr, gaddr) \
    asm volatile("cp.async.ca.shared.global [%0], [%1], 16;" \
                 :: "r"(saddr), "l"(gaddr) : "memory")
#define CP_COMMIT() asm volatile("cp.async.commit_group;" ::: "memory")
#define CP_WAIT(n)  asm volatile("cp.async.wait_group %0;" :: "n"(n) : "memory")

#define MMA_TF32(c, a0, a1, a2, a3, b0, b1) \
    asm volatile("mma.sync.aligned.m16n8k8.row.col.f32.tf32.tf32.f32 " \
                 "{%0,%1,%2,%3}, {%4,%5,%6,%7}, {%8,%9}, {%0,%1,%2,%3};" \
                 : "+f"((c)[0]), "+f"((c)[1]), "+f"((c)[2]), "+f"((c)[3]) \
                 : "r"(a0), "r"(a1), "r"(a2), "r"(a3), "r"(b0), "r"(b1))

// ---------------------------------------------------------------------------
// tf32 rounding pass
// ---------------------------------------------------------------------------
__global__ __launch_bounds__(256)
void round_tf32_kernel(const float* __restrict__ in, float* __restrict__ out, int n4) {
    int i = blockIdx.x * 256 + threadIdx.x;
    if (i >= n4) return;
    float4 v = ((const float4*)in)[i];
    v.x = rna_tf32(v.x); v.y = rna_tf32(v.y);
    v.z = rna_tf32(v.z); v.w = rna_tf32(v.w);
    ((float4*)out)[i] = v;
}

// ---------------------------------------------------------------------------
// tf32 mma.sync GEMM (NT): C[M,N] = A[M,K] * B[N,K]^T, row-major, fp32 out.
// CTA 128x128, BK=32, 256 threads (8 warps, 2x4), warp tile 64x32.
// cp.async double-buffered smem; padded rows (36 floats) -> conflict-free.
// ---------------------------------------------------------------------------
#define BM 128
#define BN 128
#define BK 32
#define SROW 36
#define TILE_F (128 * SROW)            // floats per (A or B) tile
#define STAGE_F (2 * TILE_F)           // A + B
#define STAGE_B (STAGE_F * 4)          // bytes per stage
#define GM_SMEM (2 * STAGE_B)          // 73728
#define NK (EMB / BK)                  // 64

__global__ __launch_bounds__(256, 1)
void gemm_tf32(const float* __restrict__ A, const float* __restrict__ B,
               float* __restrict__ C) {
    extern __shared__ float smf[];
    const uint32_t sb = smem_u32(smf);

    const int tid = threadIdx.x;
    const int wid = tid >> 5;
    const int lane = tid & 31;
    const int gid = lane >> 2;      // groupID 0..7
    const int tig = lane & 3;       // thread-in-group 0..3
    const int wm = wid >> 2;        // 0..1
    const int wn = wid & 3;         // 0..3
    const int bm = blockIdx.y * BM;
    const int bn = blockIdx.x * BN;

    // loader mapping: 128 rows x 8 float4-chunks per tile, 4 chunks per thread
    const int lrow0 = tid >> 3;     // +32 per step c? (we use id = tid + c*256)
    (void)lrow0;

    float acc[4][4][4];
#pragma unroll
    for (int mi = 0; mi < 4; mi++)
#pragma unroll
        for (int ni = 0; ni < 4; ni++)
#pragma unroll
            for (int q = 0; q < 4; q++) acc[mi][ni][q] = 0.0f;

    auto issue_stage = [&](int kt, int stage) {
#pragma unroll
        for (int c = 0; c < 4; c++) {
            int id = tid + c * 256;        // 0..1023
            int row = id >> 3;             // 0..127
            int cg = id & 7;               // float4 index within 32 floats
            uint32_t soff = (uint32_t)(row * SROW + cg * 4) * 4u;
            uint32_t saA = sb + stage * STAGE_B + soff;
            uint32_t saB = saA + TILE_F * 4;
            const float* gaA = A + (size_t)(bm + row) * EMB + kt * BK + cg * 4;
            const float* gaB = B + (size_t)(bn + row) * EMB + kt * BK + cg * 4;
            CP_ASYNC16(saA, gaA);
            CP_ASYNC16(saB, gaB);
        }
        CP_COMMIT();
    };

    issue_stage(0, 0);
    issue_stage(1, 1);

    for (int kt = 0; kt < NK; kt++) {
        const int s = kt & 1;
        if (kt + 1 < NK) { CP_WAIT(1); } else { CP_WAIT(0); }
        __syncthreads();

        const float* As = smf + s * STAGE_F;
        const float* Bs = As + TILE_F;
        const int am0 = wm * 64;
        const int bn0 = wn * 32;

#pragma unroll
        for (int ks = 0; ks < 4; ks++) {
            const int k0 = ks * 8;
            uint32_t a[4][4];
#pragma unroll
            for (int mi = 0; mi < 4; mi++) {
                const int r0 = am0 + mi * 16 + gid;
                a[mi][0] = __float_as_uint(As[r0 * SROW + k0 + tig]);
                a[mi][1] = __float_as_uint(As[(r0 + 8) * SROW + k0 + tig]);
                a[mi][2] = __float_as_uint(As[r0 * SROW + k0 + tig + 4]);
                a[mi][3] = __float_as_uint(As[(r0 + 8) * SROW + k0 + tig + 4]);
            }
            uint32_t b[4][2];
#pragma unroll
            for (int ni = 0; ni < 4; ni++) {
                const int n0 = bn0 + ni * 8 + gid;
                b[ni][0] = __float_as_uint(Bs[n0 * SROW + k0 + tig]);
                b[ni][1] = __float_as_uint(Bs[n0 * SROW + k0 + tig + 4]);
            }
#pragma unroll
            for (int mi = 0; mi < 4; mi++)
#pragma unroll
                for (int ni = 0; ni < 4; ni++)
                    MMA_TF32(acc[mi][ni], a[mi][0], a[mi][1], a[mi][2], a[mi][3],
                             b[ni][0], b[ni][1]);
        }
        __syncthreads();
        if (kt + 2 < NK) issue_stage(kt + 2, s);
    }

    // epilogue
#pragma unroll
    for (int mi = 0; mi < 4; mi++) {
        const int r0 = bm + wm * 64 + mi * 16 + gid;
#pragma unroll
        for (int ni = 0; ni < 4; ni++) {
            const int c0 = bn + wn * 32 + ni * 8 + tig * 2;
            float2 w0; w0.x = acc[mi][ni][0]; w0.y = acc[mi][ni][1];
            float2 w1; w1.x = acc[mi][ni][2]; w1.y = acc[mi][ni][3];
            *(float2*)(C + (size_t)r0 * EMB + c0) = w0;
            *(float2*)(C + (size_t)(r0 + 8) * EMB + c0) = w1;
        }
    }
}

// ---------------------------------------------------------------------------
// xpos rotary on q and k (in place).
// ---------------------------------------------------------------------------
__global__ __launch_bounds__(256)
void xpos_kernel() {
    int idx = blockIdx.x * 256 + threadIdx.x;
    int pair = idx & 63;
    int h = (idx >> 6) & (HEADS - 1);
    int bs = idx >> 10;
    int s = bs & (SEQ - 1);

    float seq = (float)(s - SEQ / 2) * (1.0f / 512.0f);
    float dr = 2.0f * (float)(pair + 1);
    float theta = powf(1.0e-4f, dr * (1.0f / 128.0f));
    float zeta = (dr * (1.0f / 64.0f) + 51.2f) * (1.0f / 52.2f);
    float ang = seq * theta;
    float c = cosf(ang);
    float sn = sinf(ang);
    float t = powf(zeta, seq);
    float it = 1.0f / t;

    size_t base = (size_t)bs * EMB + h * HDIM + pair * 2;
    float2 qv = *(float2*)(g_q + base);
    float2 kv = *(float2*)(g_k + base);
    float2 qo, ko;
    qo.x = (qv.x * c - qv.y * sn) * t;
    qo.y = (qv.y * c + qv.x * sn) * t;
    ko.x = (kv.x * c - kv.y * sn) * it;
    ko.y = (kv.y * c + kv.x * sn) * it;
    *(float2*)(g_q + base) = qo;
    *(float2*)(g_k + base) = ko;
}

// ---------------------------------------------------------------------------
// Causal flash attention, fp32 (epilogue rounds output to tf32).
// ---------------------------------------------------------------------------
__global__ __launch_bounds__(512, 1)
void attn_kernel() {
    extern __shared__ float smf[];
    float4* Ks4 = (float4*)smf;
    float4* Vs4 = (float4*)(smf + 64 * 128);

    const int bid = blockIdx.x;
    const int qt = (SEQ / 128 - 1) - (bid >> 5);
    const int bh = bid & 31;
    const int b = bh >> 4;
    const int h = bh & (HEADS - 1);

    const int tid = threadIdx.x;
    const int rloc = tid >> 2;
    const int g = tid & 3;
    const int r = qt * 128 + rloc;
    const unsigned gmask = 0xFu << ((tid & 31) & ~3);

    const float* qbase = g_q + ((size_t)b * SEQ + r) * EMB + h * HDIM + g * 32;
    float4 q4[8];
#pragma unroll
    for (int i = 0; i < 8; i++) q4[i] = ((const float4*)qbase)[i];

    float4 o4[8];
#pragma unroll
    for (int i = 0; i < 8; i++) o4[i] = make_float4(0.f, 0.f, 0.f, 0.f);
    float m = -3.0e38f, l = 0.0f;
    const float scale = 0.08838834764831845f;

    const float* kg = g_k + (size_t)b * SEQ * EMB + h * HDIM;
    const float* vg = g_v + (size_t)b * SEQ * EMB + h * HDIM;

    const int nkt = qt * 2 + 2;
    for (int kt = 0; kt < nkt; kt++) {
        __syncthreads();
#pragma unroll
        for (int i = 0; i < 4; i++) {
            int id = tid + i * 512;
            int row = id >> 5;
            int c4 = id & 31;
            size_t goff = (size_t)(kt * 64 + row) * EMB + c4 * 4;
            Ks4[row * 32 + c4] = *(const float4*)(kg + goff);
            Vs4[row * 32 + c4] = *(const float4*)(vg + goff);
        }
        __syncthreads();

        int jmax = r - kt * 64 + 1;
        if (jmax > 64) jmax = 64;
        for (int j = 0; j < jmax; j++) {
            const float4* krow = Ks4 + j * 32 + g * 8;
            float p0 = 0.f, p1 = 0.f, p2 = 0.f, p3 = 0.f;
#pragma unroll
            for (int i = 0; i < 8; i++) {
                float4 kv = krow[i];
                p0 = fmaf(q4[i].x, kv.x, p0);
                p1 = fmaf(q4[i].y, kv.y, p1);
                p2 = fmaf(q4[i].z, kv.z, p2);
                p3 = fmaf(q4[i].w, kv.w, p3);
            }
            float sdot = (p0 + p1) + (p2 + p3);
            sdot += __shfl_xor_sync(gmask, sdot, 1);
            sdot += __shfl_xor_sync(gmask, sdot, 2);
            float sc = sdot * scale;

            float mn = fmaxf(m, sc);
            float cf = __expf(m - mn);
            float p = __expf(sc - mn);
            l = l * cf + p;
            m = mn;

            const float4* vrow = Vs4 + j * 32 + g * 8;
#pragma unroll
            for (int i = 0; i < 8; i++) {
                float4 vv = vrow[i];
                o4[i].x = fmaf(p, vv.x, o4[i].x * cf);
                o4[i].y = fmaf(p, vv.y, o4[i].y * cf);
                o4[i].z = fmaf(p, vv.z, o4[i].z * cf);
                o4[i].w = fmaf(p, vv.w, o4[i].w * cf);
            }
        }
    }

    float inv = 1.0f / l;
    float* ob = g_att + ((size_t)b * SEQ + r) * EMB + h * HDIM + g * 32;
#pragma unroll
    for (int i = 0; i < 8; i++) {
        float4 w;
        w.x = rna_tf32(o4[i].x * inv);
        w.y = rna_tf32(o4[i].y * inv);
        w.z = rna_tf32(o4[i].z * inv);
        w.w = rna_tf32(o4[i].w * inv);
        ((float4*)ob)[i] = w;
    }
}

// ---------------------------------------------------------------------------
// Launch
// ---------------------------------------------------------------------------
extern "C" void kernel_launch(void* const* d_in, const int* in_sizes, int n_in,
                              void* d_out, int out_size) {
    const float* act = (const float*)d_in[0];
    const float* Wq  = (const float*)d_in[1];
    const float* Wk  = (const float*)d_in[2];
    const float* Wv  = (const float*)d_in[3];
    const float* Wo  = (const float*)d_in[4];
    float* out = (float*)d_out;

    float *qp, *kp, *vp, *ap, *actr, *wr;
    cudaGetSymbolAddress((void**)&qp, g_q);
    cudaGetSymbolAddress((void**)&kp, g_k);
    cudaGetSymbolAddress((void**)&vp, g_v);
    cudaGetSymbolAddress((void**)&ap, g_att);
    cudaGetSymbolAddress((void**)&actr, g_actr);
    cudaGetSymbolAddress((void**)&wr, g_w);

    cudaFuncSetAttribute(gemm_tf32, cudaFuncAttributeMaxDynamicSharedMemorySize, GM_SMEM);
    cudaFuncSetAttribute(attn_kernel, cudaFuncAttributeMaxDynamicSharedMemorySize,
                         64 * 128 * 4 * 2);

    const int nw4 = EMB * EMB / 4;
    const int na4 = BATCH * SEQ * EMB / 4;
    dim3 ggrid(EMB / BN, BATCH * SEQ / BM);   // (16, 32)

    round_tf32_kernel<<<(na4 + 255) / 256, 256>>>(act, actr, na4);

    round_tf32_kernel<<<(nw4 + 255) / 256, 256>>>(Wq, wr, nw4);
    gemm_tf32<<<ggrid, 256, GM_SMEM>>>(actr, wr, qp);

    round_tf32_kernel<<<(nw4 + 255) / 256, 256>>>(Wk, wr, nw4);
    gemm_tf32<<<ggrid, 256, GM_SMEM>>>(actr, wr, kp);

    round_tf32_kernel<<<(nw4 + 255) / 256, 256>>>(Wv, wr, nw4);
    gemm_tf32<<<ggrid, 256, GM_SMEM>>>(actr, wr, vp);

    int nrot = BATCH * SEQ * HEADS * 64;
    xpos_kernel<<<nrot / 256, 256>>>();

    attn_kernel<<<BATCH * HEADS * (SEQ / 128), 512, 64 * 128 * 4 * 2>>>();

    round_tf32_kernel<<<(nw4 + 255) / 256, 256>>>(Wo, wr, nw4);
    gemm_tf32<<<ggrid, 256, GM_SMEM>>>(ap, wr, out);
}